// round 1
// baseline (speedup 1.0000x reference)
#include <cuda_runtime.h>
#include <math.h>

#define H   1024
#define NC  2048
#define BB  8192
#define H2  2048
#define H3  3072

// ---------------- scratch (no allocations allowed) ----------------
__device__ float gOutT [(size_t)NC * NC];   // in_matrix^T
__device__ float gInit [(size_t)NC * H];    // last_fc_weight^T
__device__ float gNodes[(size_t)NC * H];
__device__ float gU    [(size_t)NC * H3];   // [in@n | out@n | n or rv*n]
__device__ float gW3   [(size_t)H3 * H];
__device__ float gW4   [(size_t)H3 * H];
__device__ float gW5   [(size_t)H3 * H];
__device__ float gZ    [(size_t)NC * H];
__device__ float gR    [(size_t)NC * H];
__device__ float gHh   [(size_t)NC * H];
__device__ float gV    [(size_t)NC * H2];   // [nodes | init_nodes]
__device__ float gS    [(size_t)NC * H];    // step_out
__device__ float gWt   [(size_t)H * NC];    // step_out^T
__device__ float gPart [256];

// ---------------- SGEMM: C[M,N] = act(A[M,K] @ B[K,N] (+bias)) ----------------
// BM=BN=128, BK=16, 256 threads, 8x8 per thread. All dims multiples of 128/16.
// ACT: 0 none, 1 sigmoid, 2 tanh
template <int ACT>
__global__ __launch_bounds__(256, 2)
void sgemm128(const float* __restrict__ A, const float* __restrict__ B,
              float* __restrict__ C, int M, int N, int K, int ldc,
              const float* __restrict__ bias)
{
    __shared__ float As[16][128];
    __shared__ float Bs[16][128];

    const int tid = threadIdx.x;
    const int tm  = tid >> 4;          // 0..15
    const int tn  = tid & 15;          // 0..15
    const int bx  = blockIdx.x;        // N tiles
    const int by  = blockIdx.y;        // M tiles

    const float* Aptr = A + (size_t)(by * 128) * K;
    const float* Bptr = B + (size_t)(bx * 128);

    float acc[8][8];
#pragma unroll
    for (int i = 0; i < 8; i++)
#pragma unroll
        for (int j = 0; j < 8; j++) acc[i][j] = 0.f;

    for (int k0 = 0; k0 < K; k0 += 16) {
        // load A tile 128x16 (transposed into As[k][m])
#pragma unroll
        for (int l = 0; l < 2; l++) {
            int idx = tid + l * 256;
            int row = idx >> 2;
            int col = (idx & 3) << 2;
            float4 v = *(const float4*)(Aptr + (size_t)row * K + k0 + col);
            As[col + 0][row] = v.x;
            As[col + 1][row] = v.y;
            As[col + 2][row] = v.z;
            As[col + 3][row] = v.w;
        }
        // load B tile 16x128
#pragma unroll
        for (int l = 0; l < 2; l++) {
            int idx = tid + l * 256;
            int row = idx >> 5;
            int col = (idx & 31) << 2;
            *(float4*)(&Bs[row][col]) =
                *(const float4*)(Bptr + (size_t)(k0 + row) * N + col);
        }
        __syncthreads();

#pragma unroll
        for (int k = 0; k < 16; k++) {
            float a[8], b[8];
            *(float4*)(a)     = *(float4*)(&As[k][tm * 8]);
            *(float4*)(a + 4) = *(float4*)(&As[k][tm * 8 + 4]);
            *(float4*)(b)     = *(float4*)(&Bs[k][tn * 8]);
            *(float4*)(b + 4) = *(float4*)(&Bs[k][tn * 8 + 4]);
#pragma unroll
            for (int i = 0; i < 8; i++)
#pragma unroll
                for (int j = 0; j < 8; j++)
                    acc[i][j] = fmaf(a[i], b[j], acc[i][j]);
        }
        __syncthreads();
    }

    const int crow0 = by * 128 + tm * 8;
    const int ccol0 = bx * 128 + tn * 8;
    float bj[8];
    if (bias) {
#pragma unroll
        for (int j = 0; j < 8; j++) bj[j] = bias[ccol0 + j];
    }
#pragma unroll
    for (int i = 0; i < 8; i++) {
        float v[8];
#pragma unroll
        for (int j = 0; j < 8; j++) {
            float t = acc[i][j];
            if (bias) t += bj[j];
            if (ACT == 1) t = 1.f / (1.f + expf(-t));
            if (ACT == 2) t = tanhf(t);
            v[j] = t;
        }
        float* cp = C + (size_t)(crow0 + i) * ldc + ccol0;
        *(float4*)(cp)     = make_float4(v[0], v[1], v[2], v[3]);
        *(float4*)(cp + 4) = make_float4(v[4], v[5], v[6], v[7]);
    }
}

// ---------------- transpose: dst[C,R] = src[R,C]^T ----------------
__global__ void transpose_k(const float* __restrict__ src, float* __restrict__ dst,
                            int R, int C)
{
    __shared__ float t[32][33];
    int c = blockIdx.x * 32 + threadIdx.x;
    int r = blockIdx.y * 32 + threadIdx.y;
#pragma unroll
    for (int i = 0; i < 32; i += 8)
        if (r + i < R && c < C) t[threadIdx.y + i][threadIdx.x] = src[(size_t)(r + i) * C + c];
    __syncthreads();
    int c2 = blockIdx.y * 32 + threadIdx.x;
    int r2 = blockIdx.x * 32 + threadIdx.y;
#pragma unroll
    for (int i = 0; i < 32; i += 8)
        if (r2 + i < C && c2 < R) dst[(size_t)(r2 + i) * R + c2] = t[threadIdx.x][threadIdx.y + i];
}

// copy contiguous src[NC,w] into strided dst (row stride ld)
__global__ void colcopy_k(const float* __restrict__ src, float* __restrict__ dst,
                          int w, int ld, long n)
{
    long i = (long)blockIdx.x * 256 + threadIdx.x;
    if (i < n) {
        long r = i / w, c = i - r * w;
        dst[r * ld + c] = src[i];
    }
}

// U[:,2h:3h] = R * nodes
__global__ void rnmul_k(const float* __restrict__ Rv, const float* __restrict__ Nd,
                        float* __restrict__ Uslot)
{
    long i = (long)blockIdx.x * 256 + threadIdx.x;
    if (i < (long)NC * H) {
        long r = i / H, c = i - r * H;
        Uslot[r * H3 + c] = Rv[i] * Nd[i];
    }
}

// nodes = (1-z)*nodes + z*h ; also refresh U[:,2h:3h]
__global__ void update_k(const float* __restrict__ Zv, const float* __restrict__ Hv,
                         float* __restrict__ Nd, float* __restrict__ Uslot)
{
    long i = (long)blockIdx.x * 256 + threadIdx.x;
    if (i < (long)NC * H) {
        float z = Zv[i];
        float nv = (1.f - z) * Nd[i] + z * Hv[i];
        Nd[i] = nv;
        long r = i / H, c = i - r * H;
        Uslot[r * H3 + c] = nv;
    }
}

// deterministic two-pass sum of squares
__global__ void l2part_k(const float* __restrict__ S, long n, float* __restrict__ part)
{
    __shared__ float sm[256];
    float s = 0.f;
    for (long i = (long)blockIdx.x * 256 + threadIdx.x; i < n; i += 256L * 256L) {
        float v = S[i];
        s = fmaf(v, v, s);
    }
    sm[threadIdx.x] = s;
    __syncthreads();
    for (int o = 128; o > 0; o >>= 1) {
        if (threadIdx.x < o) sm[threadIdx.x] += sm[threadIdx.x + o];
        __syncthreads();
    }
    if (threadIdx.x == 0) part[blockIdx.x] = sm[0];
}

__global__ void l2final_k(const float* __restrict__ part, float* __restrict__ out)
{
    __shared__ float sm[256];
    sm[threadIdx.x] = part[threadIdx.x];
    __syncthreads();
    for (int o = 128; o > 0; o >>= 1) {
        if (threadIdx.x < o) sm[threadIdx.x] += sm[threadIdx.x + o];
        __syncthreads();
    }
    if (threadIdx.x == 0) out[0] = sm[0];
}

// ---------------- launch ----------------
extern "C" void kernel_launch(void* const* d_in, const int* in_sizes, int n_in,
                              void* d_out, int out_size)
{
    const float* x   = (const float*)d_in[0];   // [B, h]
    const float* lfw = (const float*)d_in[1];   // [h, N]
    const float* inm = (const float*)d_in[2];   // [N, N]
    const float* w3w = (const float*)d_in[3];   // [2h, h]
    const float* w3u = (const float*)d_in[4];   // [h, h]
    const float* w4w = (const float*)d_in[5];
    const float* w4u = (const float*)d_in[6];
    const float* w5w = (const float*)d_in[7];
    const float* w5u = (const float*)d_in[8];
    const float* fcw = (const float*)d_in[9];   // [2h, h]
    const float* fcb = (const float*)d_in[10];  // [h]
    float* out = (float*)d_out;

    float *pOutT, *pInit, *pNodes, *pU, *pW3, *pW4, *pW5, *pZ, *pR, *pH, *pV, *pS, *pWt, *pPart;
    cudaGetSymbolAddress((void**)&pOutT, gOutT);
    cudaGetSymbolAddress((void**)&pInit, gInit);
    cudaGetSymbolAddress((void**)&pNodes, gNodes);
    cudaGetSymbolAddress((void**)&pU, gU);
    cudaGetSymbolAddress((void**)&pW3, gW3);
    cudaGetSymbolAddress((void**)&pW4, gW4);
    cudaGetSymbolAddress((void**)&pW5, gW5);
    cudaGetSymbolAddress((void**)&pZ, gZ);
    cudaGetSymbolAddress((void**)&pR, gR);
    cudaGetSymbolAddress((void**)&pH, gHh);
    cudaGetSymbolAddress((void**)&pV, gV);
    cudaGetSymbolAddress((void**)&pS, gS);
    cudaGetSymbolAddress((void**)&pWt, gWt);
    cudaGetSymbolAddress((void**)&pPart, gPart);

    const size_t F = sizeof(float);

    // concatenated gate weights [Wxw ; Wxu] -> [3h, h]
    cudaMemcpyAsync(pW3,                 w3w, (size_t)H2 * H * F, cudaMemcpyDeviceToDevice, 0);
    cudaMemcpyAsync(pW3 + (size_t)H2 * H, w3u, (size_t)H  * H * F, cudaMemcpyDeviceToDevice, 0);
    cudaMemcpyAsync(pW4,                 w4w, (size_t)H2 * H * F, cudaMemcpyDeviceToDevice, 0);
    cudaMemcpyAsync(pW4 + (size_t)H2 * H, w4u, (size_t)H  * H * F, cudaMemcpyDeviceToDevice, 0);
    cudaMemcpyAsync(pW5,                 w5w, (size_t)H2 * H * F, cudaMemcpyDeviceToDevice, 0);
    cudaMemcpyAsync(pW5 + (size_t)H2 * H, w5u, (size_t)H  * H * F, cudaMemcpyDeviceToDevice, 0);

    dim3 tb(32, 8);
    transpose_k<<<dim3(NC / 32, NC / 32), tb>>>(inm, pOutT, NC, NC);   // out_matrix
    transpose_k<<<dim3(NC / 32, H  / 32), tb>>>(lfw, pInit, H, NC);    // init_nodes [N,h]

    cudaMemcpyAsync(pNodes, pInit, (size_t)NC * H * F, cudaMemcpyDeviceToDevice, 0);

    const long nh = (long)NC * H;
    const int ewg = (int)((nh + 255) / 256);
    colcopy_k<<<ewg, 256>>>(pInit, pU + H2, H, H3, nh);  // U slot3 = nodes(0)

    dim3 g_nh(H / 128, NC / 128);     // GEMMs producing [N, h]

    for (int t = 0; t < 3; t++) {
        sgemm128<0><<<g_nh, 256>>>(inm,  pNodes, pU,      NC, H, NC, H3, nullptr);
        sgemm128<0><<<g_nh, 256>>>(pOutT, pNodes, pU + H, NC, H, NC, H3, nullptr);
        sgemm128<1><<<g_nh, 256>>>(pU, pW3, pZ, NC, H, H3, H, nullptr);  // zv
        sgemm128<1><<<g_nh, 256>>>(pU, pW4, pR, NC, H, H3, H, nullptr);  // rv
        rnmul_k<<<ewg, 256>>>(pR, pNodes, pU + H2);                      // slot3 = rv*nodes
        sgemm128<2><<<g_nh, 256>>>(pU, pW5, pH, NC, H, H3, H, nullptr);  // hv
        update_k<<<ewg, 256>>>(pZ, pH, pNodes, pU + H2);                 // nodes & slot3
    }

    // step_out = [nodes | init] @ fc_out_w + b
    colcopy_k<<<ewg, 256>>>(pNodes, pV,     H, H2, nh);
    colcopy_k<<<ewg, 256>>>(pInit,  pV + H, H, H2, nh);
    sgemm128<0><<<g_nh, 256>>>(pV, fcw, pS, NC, H, H2, H, fcb);

    // weight = step_out^T ; output = x @ weight
    transpose_k<<<dim3(H / 32, NC / 32), tb>>>(pS, pWt, NC, H);
    sgemm128<0><<<dim3(NC / 128, BB / 128), 256>>>(x, pWt, out, BB, NC, H, NC, nullptr);

    // l2_reg = sum(step_out^2) -> appended scalar
    l2part_k<<<256, 256>>>(pS, nh, pPart);
    if ((long)out_size > (long)BB * NC)
        l2final_k<<<1, 256>>>(pPart, out + (size_t)BB * NC);
}

// round 2
// speedup vs baseline: 3.4476x; 3.4476x over previous
#include <cuda_runtime.h>
#include <math.h>
#include <stdint.h>

#define H   1024
#define NC  2048
#define BB  8192
#define H2  2048
#define H3  3072

#define BM 128
#define BN 128
#define BK 32
#define ASTRIDE 36    // BK + 4 : frag bank = (4m+k)%32, conflict-free
#define BSTRIDE 136   // BN + 8 : frag bank = (8k+n)%32, conflict-free
#define A_STAGE (BM * ASTRIDE)          // 4608 floats
#define B_STAGE (BK * BSTRIDE)          // 4352 floats
#define SMEM_FLOATS (2 * A_STAGE + 2 * B_STAGE)
#define SMEM_BYTES (SMEM_FLOATS * 4)    // 71680 B

// ---------------- scratch (no allocations allowed) ----------------
__device__ float gOutT [(size_t)NC * NC];   // in_matrix^T
__device__ float gInit [(size_t)NC * H];    // last_fc_weight^T
__device__ float gNodes[(size_t)NC * H];
__device__ float gU    [(size_t)NC * H3];   // [in@n | out@n | n or rv*n]
__device__ float gW3   [(size_t)H3 * H];
__device__ float gW4   [(size_t)H3 * H];
__device__ float gW5   [(size_t)H3 * H];
__device__ float gZ    [(size_t)NC * H];
__device__ float gR    [(size_t)NC * H];
__device__ float gHh   [(size_t)NC * H];
__device__ float gV    [(size_t)NC * H2];   // [nodes | init_nodes]
__device__ float gS    [(size_t)NC * H];    // step_out
__device__ float gWt   [(size_t)H * NC];    // step_out^T
__device__ float gPart [256];

// ---------------- helpers ----------------
__device__ __forceinline__ uint32_t f2tf32(float x) {
    uint32_t r;
    asm volatile("cvt.rna.tf32.f32 %0, %1;\n" : "=r"(r) : "f"(x));
    return r;
}

__device__ __forceinline__ void cpasync16(float* dst_smem, const float* src) {
    uint32_t d = (uint32_t)__cvta_generic_to_shared(dst_smem);
    asm volatile("cp.async.cg.shared.global [%0], [%1], 16;\n" :: "r"(d), "l"(src));
}

__device__ __forceinline__ void mma_tf32(float c[4], const uint32_t a[4], const uint32_t b[2]) {
    asm volatile(
        "mma.sync.aligned.m16n8k8.row.col.f32.tf32.tf32.f32 "
        "{%0,%1,%2,%3}, {%4,%5,%6,%7}, {%8,%9}, {%0,%1,%2,%3};\n"
        : "+f"(c[0]), "+f"(c[1]), "+f"(c[2]), "+f"(c[3])
        : "r"(a[0]), "r"(a[1]), "r"(a[2]), "r"(a[3]), "r"(b[0]), "r"(b[1]));
}

// ---------------- TF32 MMA GEMM: C[M,N] = act(A[M,K] @ B[K,N] (+bias)) ----------------
// BM=BN=128, BK=32, 256 threads (8 warps, warp tile 64x32).
// M,N multiples of 128; K multiple of 32.  ACT: 0 none, 1 sigmoid, 2 tanh.
template <int ACT>
__global__ __launch_bounds__(256)
void gemm_tf32(const float* __restrict__ A, const float* __restrict__ B,
               float* __restrict__ C, int M, int N, int K, int ldc,
               const float* __restrict__ bias)
{
    extern __shared__ float sm[];
    float* AsBase = sm;                 // [2][BM][ASTRIDE]
    float* BsBase = sm + 2 * A_STAGE;   // [2][BK][BSTRIDE]

    const int tid  = threadIdx.x;
    const int wid  = tid >> 5;
    const int lane = tid & 31;
    const int wm   = (wid >> 2) * 64;   // 0 / 64
    const int wn   = (wid & 3) * 32;    // 0..96
    const int lr   = lane >> 2;         // 0..7
    const int lc   = lane & 3;          // 0..3

    const int brow = blockIdx.y * BM;
    const int bcol = blockIdx.x * BN;

    const float* Ag = A + (size_t)brow * K;
    const float* Bg = B + bcol;

    float acc[4][4][4];
#pragma unroll
    for (int mi = 0; mi < 4; mi++)
#pragma unroll
        for (int ni = 0; ni < 4; ni++)
#pragma unroll
            for (int e = 0; e < 4; e++) acc[mi][ni][e] = 0.f;

    const int ntiles = K / BK;

    // ---- tile loader via cp.async ----
    // A tile: 128 rows x 32 k -> m-major As[m][k]; 1024 16B chunks, 4/thread
    // B tile: 32 k x 128 n    -> k-major Bs[k][n]; 1024 16B chunks, 4/thread
#define LOAD_TILE(kt, stg)                                                      \
    {                                                                           \
        const int k0 = (kt) * BK;                                               \
        float* As_ = AsBase + (stg) * A_STAGE;                                  \
        float* Bs_ = BsBase + (stg) * B_STAGE;                                  \
        _Pragma("unroll")                                                       \
        for (int i = 0; i < 4; i++) {                                           \
            int c   = tid + i * 256;                                            \
            int row = c >> 3;                                                   \
            int kc  = (c & 7) * 4;                                              \
            cpasync16(As_ + row * ASTRIDE + kc, Ag + (size_t)row * K + k0 + kc);\
        }                                                                       \
        _Pragma("unroll")                                                       \
        for (int i = 0; i < 4; i++) {                                           \
            int c   = tid + i * 256;                                            \
            int row = c >> 5;                                                   \
            int nc  = (c & 31) * 4;                                             \
            cpasync16(Bs_ + row * BSTRIDE + nc, Bg + (size_t)(k0 + row) * N + nc);\
        }                                                                       \
        asm volatile("cp.async.commit_group;\n" ::: "memory");                  \
    }

    LOAD_TILE(0, 0);

    for (int kt = 0; kt < ntiles; kt++) {
        const int cur = kt & 1;
        if (kt + 1 < ntiles) {
            LOAD_TILE(kt + 1, (kt + 1) & 1);
            asm volatile("cp.async.wait_group 1;\n" ::: "memory");
        } else {
            asm volatile("cp.async.wait_group 0;\n" ::: "memory");
        }
        __syncthreads();

        const float* As_ = AsBase + cur * A_STAGE;
        const float* Bs_ = BsBase + cur * B_STAGE;

#pragma unroll
        for (int ks = 0; ks < BK / 8; ks++) {
            const int kk = ks * 8;
            uint32_t a[4][4];
#pragma unroll
            for (int mi = 0; mi < 4; mi++) {
                const float* ap = As_ + (wm + mi * 16 + lr) * ASTRIDE + kk;
                a[mi][0] = f2tf32(ap[lc]);
                a[mi][1] = f2tf32(ap[8 * ASTRIDE + lc]);
                a[mi][2] = f2tf32(ap[lc + 4]);
                a[mi][3] = f2tf32(ap[8 * ASTRIDE + lc + 4]);
            }
            uint32_t b[4][2];
#pragma unroll
            for (int ni = 0; ni < 4; ni++) {
                const float* bp = Bs_ + (kk + lc) * BSTRIDE + wn + ni * 8 + lr;
                b[ni][0] = f2tf32(bp[0]);
                b[ni][1] = f2tf32(bp[4 * BSTRIDE]);
            }
#pragma unroll
            for (int mi = 0; mi < 4; mi++)
#pragma unroll
                for (int ni = 0; ni < 4; ni++)
                    mma_tf32(acc[mi][ni], a[mi], b[ni]);
        }
        __syncthreads();
    }
#undef LOAD_TILE

    // ---- epilogue ----
#pragma unroll
    for (int mi = 0; mi < 4; mi++) {
        const int r0 = brow + wm + mi * 16 + lr;
#pragma unroll
        for (int ni = 0; ni < 4; ni++) {
            const int col = bcol + wn + ni * 8 + lc * 2;
            float v[4];
#pragma unroll
            for (int e = 0; e < 4; e++) v[e] = acc[mi][ni][e];
            if (bias) {
                float b0 = bias[col], b1 = bias[col + 1];
                v[0] += b0; v[1] += b1; v[2] += b0; v[3] += b1;
            }
#pragma unroll
            for (int e = 0; e < 4; e++) {
                if (ACT == 1) v[e] = 1.f / (1.f + expf(-v[e]));
                if (ACT == 2) v[e] = tanhf(v[e]);
            }
            *(float2*)(C + (size_t)r0 * ldc + col)       = make_float2(v[0], v[1]);
            *(float2*)(C + (size_t)(r0 + 8) * ldc + col) = make_float2(v[2], v[3]);
        }
    }
}

// ---------------- transpose: dst[C,R] = src[R,C]^T ----------------
__global__ void transpose_k(const float* __restrict__ src, float* __restrict__ dst,
                            int R, int C)
{
    __shared__ float t[32][33];
    int c = blockIdx.x * 32 + threadIdx.x;
    int r = blockIdx.y * 32 + threadIdx.y;
#pragma unroll
    for (int i = 0; i < 32; i += 8)
        if (r + i < R && c < C) t[threadIdx.y + i][threadIdx.x] = src[(size_t)(r + i) * C + c];
    __syncthreads();
    int c2 = blockIdx.y * 32 + threadIdx.x;
    int r2 = blockIdx.x * 32 + threadIdx.y;
#pragma unroll
    for (int i = 0; i < 32; i += 8)
        if (r2 + i < C && c2 < R) dst[(size_t)(r2 + i) * R + c2] = t[threadIdx.x][threadIdx.y + i];
}

// copy contiguous src[NC,w] into strided dst (row stride ld)
__global__ void colcopy_k(const float* __restrict__ src, float* __restrict__ dst,
                          int w, int ld, long n)
{
    long i = (long)blockIdx.x * 256 + threadIdx.x;
    if (i < n) {
        long r = i / w, c = i - r * w;
        dst[r * ld + c] = src[i];
    }
}

// U[:,2h:3h] = R * nodes
__global__ void rnmul_k(const float* __restrict__ Rv, const float* __restrict__ Nd,
                        float* __restrict__ Uslot)
{
    long i = (long)blockIdx.x * 256 + threadIdx.x;
    if (i < (long)NC * H) {
        long r = i / H, c = i - r * H;
        Uslot[r * H3 + c] = Rv[i] * Nd[i];
    }
}

// nodes = (1-z)*nodes + z*h ; also refresh U[:,2h:3h]
__global__ void update_k(const float* __restrict__ Zv, const float* __restrict__ Hv,
                         float* __restrict__ Nd, float* __restrict__ Uslot)
{
    long i = (long)blockIdx.x * 256 + threadIdx.x;
    if (i < (long)NC * H) {
        float z = Zv[i];
        float nv = (1.f - z) * Nd[i] + z * Hv[i];
        Nd[i] = nv;
        long r = i / H, c = i - r * H;
        Uslot[r * H3 + c] = nv;
    }
}

// deterministic two-pass sum of squares
__global__ void l2part_k(const float* __restrict__ S, long n, float* __restrict__ part)
{
    __shared__ float sm[256];
    float s = 0.f;
    for (long i = (long)blockIdx.x * 256 + threadIdx.x; i < n; i += 256L * 256L) {
        float v = S[i];
        s = fmaf(v, v, s);
    }
    sm[threadIdx.x] = s;
    __syncthreads();
    for (int o = 128; o > 0; o >>= 1) {
        if (threadIdx.x < o) sm[threadIdx.x] += sm[threadIdx.x + o];
        __syncthreads();
    }
    if (threadIdx.x == 0) part[blockIdx.x] = sm[0];
}

__global__ void l2final_k(const float* __restrict__ part, float* __restrict__ out)
{
    __shared__ float sm[256];
    sm[threadIdx.x] = part[threadIdx.x];
    __syncthreads();
    for (int o = 128; o > 0; o >>= 1) {
        if (threadIdx.x < o) sm[threadIdx.x] += sm[threadIdx.x + o];
        __syncthreads();
    }
    if (threadIdx.x == 0) out[0] = sm[0];
}

// ---------------- launch ----------------
extern "C" void kernel_launch(void* const* d_in, const int* in_sizes, int n_in,
                              void* d_out, int out_size)
{
    const float* x   = (const float*)d_in[0];   // [B, h]
    const float* lfw = (const float*)d_in[1];   // [h, N]
    const float* inm = (const float*)d_in[2];   // [N, N]
    const float* w3w = (const float*)d_in[3];   // [2h, h]
    const float* w3u = (const float*)d_in[4];   // [h, h]
    const float* w4w = (const float*)d_in[5];
    const float* w4u = (const float*)d_in[6];
    const float* w5w = (const float*)d_in[7];
    const float* w5u = (const float*)d_in[8];
    const float* fcw = (const float*)d_in[9];   // [2h, h]
    const float* fcb = (const float*)d_in[10];  // [h]
    float* out = (float*)d_out;

    float *pOutT, *pInit, *pNodes, *pU, *pW3, *pW4, *pW5, *pZ, *pR, *pH, *pV, *pS, *pWt, *pPart;
    cudaGetSymbolAddress((void**)&pOutT, gOutT);
    cudaGetSymbolAddress((void**)&pInit, gInit);
    cudaGetSymbolAddress((void**)&pNodes, gNodes);
    cudaGetSymbolAddress((void**)&pU, gU);
    cudaGetSymbolAddress((void**)&pW3, gW3);
    cudaGetSymbolAddress((void**)&pW4, gW4);
    cudaGetSymbolAddress((void**)&pW5, gW5);
    cudaGetSymbolAddress((void**)&pZ, gZ);
    cudaGetSymbolAddress((void**)&pR, gR);
    cudaGetSymbolAddress((void**)&pH, gHh);
    cudaGetSymbolAddress((void**)&pV, gV);
    cudaGetSymbolAddress((void**)&pS, gS);
    cudaGetSymbolAddress((void**)&pWt, gWt);
    cudaGetSymbolAddress((void**)&pPart, gPart);

    // opt-in dynamic smem (idempotent, host-side; legal during capture)
    cudaFuncSetAttribute(gemm_tf32<0>, cudaFuncAttributeMaxDynamicSharedMemorySize, SMEM_BYTES);
    cudaFuncSetAttribute(gemm_tf32<1>, cudaFuncAttributeMaxDynamicSharedMemorySize, SMEM_BYTES);
    cudaFuncSetAttribute(gemm_tf32<2>, cudaFuncAttributeMaxDynamicSharedMemorySize, SMEM_BYTES);

    const size_t F = sizeof(float);

    // concatenated gate weights [Wxw ; Wxu] -> [3h, h]
    cudaMemcpyAsync(pW3,                  w3w, (size_t)H2 * H * F, cudaMemcpyDeviceToDevice, 0);
    cudaMemcpyAsync(pW3 + (size_t)H2 * H, w3u, (size_t)H  * H * F, cudaMemcpyDeviceToDevice, 0);
    cudaMemcpyAsync(pW4,                  w4w, (size_t)H2 * H * F, cudaMemcpyDeviceToDevice, 0);
    cudaMemcpyAsync(pW4 + (size_t)H2 * H, w4u, (size_t)H  * H * F, cudaMemcpyDeviceToDevice, 0);
    cudaMemcpyAsync(pW5,                  w5w, (size_t)H2 * H * F, cudaMemcpyDeviceToDevice, 0);
    cudaMemcpyAsync(pW5 + (size_t)H2 * H, w5u, (size_t)H  * H * F, cudaMemcpyDeviceToDevice, 0);

    dim3 tb(32, 8);
    transpose_k<<<dim3(NC / 32, NC / 32), tb>>>(inm, pOutT, NC, NC);   // out_matrix
    transpose_k<<<dim3(NC / 32, H  / 32), tb>>>(lfw, pInit, H, NC);    // init_nodes [N,h]

    cudaMemcpyAsync(pNodes, pInit, (size_t)NC * H * F, cudaMemcpyDeviceToDevice, 0);

    const long nh = (long)NC * H;
    const int ewg = (int)((nh + 255) / 256);
    colcopy_k<<<ewg, 256>>>(pInit, pU + H2, H, H3, nh);  // U slot3 = nodes(0)

    dim3 g_nh(H / 128, NC / 128);     // GEMMs producing [N, h]

    for (int t = 0; t < 3; t++) {
        gemm_tf32<0><<<g_nh, 256, SMEM_BYTES>>>(inm,   pNodes, pU,      NC, H, NC, H3, nullptr);
        gemm_tf32<0><<<g_nh, 256, SMEM_BYTES>>>(pOutT, pNodes, pU + H,  NC, H, NC, H3, nullptr);
        gemm_tf32<1><<<g_nh, 256, SMEM_BYTES>>>(pU, pW3, pZ, NC, H, H3, H, nullptr);  // zv
        gemm_tf32<1><<<g_nh, 256, SMEM_BYTES>>>(pU, pW4, pR, NC, H, H3, H, nullptr);  // rv
        rnmul_k<<<ewg, 256>>>(pR, pNodes, pU + H2);                                   // slot3 = rv*nodes
        gemm_tf32<2><<<g_nh, 256, SMEM_BYTES>>>(pU, pW5, pH, NC, H, H3, H, nullptr);  // hv
        update_k<<<ewg, 256>>>(pZ, pH, pNodes, pU + H2);                              // nodes & slot3
    }

    // step_out = [nodes | init] @ fc_out_w + b
    colcopy_k<<<ewg, 256>>>(pNodes, pV,     H, H2, nh);
    colcopy_k<<<ewg, 256>>>(pInit,  pV + H, H, H2, nh);
    gemm_tf32<0><<<g_nh, 256, SMEM_BYTES>>>(pV, fcw, pS, NC, H, H2, H, fcb);

    // weight = step_out^T ; output = x @ weight
    transpose_k<<<dim3(H / 32, NC / 32), tb>>>(pS, pWt, NC, H);
    gemm_tf32<0><<<dim3(NC / 128, BB / 128), 256, SMEM_BYTES>>>(x, pWt, out, BB, NC, H, NC, nullptr);

    // l2_reg = sum(step_out^2) -> appended scalar
    l2part_k<<<256, 256>>>(pS, nh, pPart);
    if ((long)out_size > (long)BB * NC)
        l2final_k<<<1, 256>>>(pPart, out + (size_t)BB * NC);
}

// round 6
// speedup vs baseline: 3.7737x; 1.0946x over previous
#include <cuda_runtime.h>
#include <math.h>
#include <stdint.h>

#define H   1024
#define NC  2048
#define BB  8192
#define H2  2048
#define H3  3072

#define BM 128
#define BN 128
#define BK 32
#define ASTRIDE 36    // BK + 4 : frag bank = (4m+k)%32, conflict-free
#define BSTRIDE 136   // BN + 8 : frag bank = (8k+n)%32, conflict-free
#define A_STAGE (BM * ASTRIDE)          // 4608 floats
#define B_STAGE (BK * BSTRIDE)          // 4352 floats
#define SMEM_FLOATS (2 * A_STAGE + 2 * B_STAGE)
#define SMEM_BYTES (SMEM_FLOATS * 4)    // 71680 B

// ---------------- scratch (no allocations allowed) ----------------
// All "R"-suffixed / GEMM-operand buffers hold tf32-RNA pre-rounded fp32 bits.
__device__ float gInR  [(size_t)NC * NC];   // round(in_matrix)
__device__ float gOutT [(size_t)NC * NC];   // round(in_matrix^T)
__device__ float gInit [(size_t)NC * H];    // last_fc_weight^T (full precision)
__device__ float gNodes[(size_t)NC * H];    // full precision state
__device__ float gNodesR[(size_t)NC * H];   // round(nodes) — GEMM B operand
__device__ float gU    [(size_t)NC * H3];   // rounded [in@n | out@n | n or rv*n]
__device__ float gW34  [(size_t)H3 * H2];   // rounded [w3w|w4w ; w3u|w4u]
__device__ float gW5   [(size_t)H3 * H];    // rounded [w5w ; w5u]
__device__ float gFcw  [(size_t)H2 * H];    // rounded fc_out_w
__device__ float gZR   [(size_t)NC * H2];   // sigmoid outputs [z | r] (full)
__device__ float gHh   [(size_t)NC * H];    // tanh output (full)
__device__ float gV    [(size_t)NC * H2];   // rounded [nodes | init]
__device__ float gS    [(size_t)NC * H];    // step_out (full, for l2)
__device__ float gWt   [(size_t)H * NC];    // rounded step_out^T
__device__ float gXr   [(size_t)BB * H];    // rounded x
__device__ float gPart [256];

// ---------------- helpers ----------------
__device__ __forceinline__ uint32_t f2tf32(float x) {
    uint32_t r;
    asm volatile("cvt.rna.tf32.f32 %0, %1;\n" : "=r"(r) : "f"(x));
    return r;
}
__device__ __forceinline__ float roundtf(float x) { return __uint_as_float(f2tf32(x)); }

__device__ __forceinline__ void cpasync16(float* dst_smem, const float* src) {
    uint32_t d = (uint32_t)__cvta_generic_to_shared(dst_smem);
    asm volatile("cp.async.cg.shared.global [%0], [%1], 16;\n" :: "r"(d), "l"(src));
}

__device__ __forceinline__ void mma_tf32(float c[4], const uint32_t a[4], const uint32_t b[2]) {
    asm volatile(
        "mma.sync.aligned.m16n8k8.row.col.f32.tf32.tf32.f32 "
        "{%0,%1,%2,%3}, {%4,%5,%6,%7}, {%8,%9}, {%0,%1,%2,%3};\n"
        : "+f"(c[0]), "+f"(c[1]), "+f"(c[2]), "+f"(c[3])
        : "r"(a[0]), "r"(a[1]), "r"(a[2]), "r"(a[3]), "r"(b[0]), "r"(b[1]));
}

// ---------------- TF32 MMA GEMM: C = act(A @ B (+bias)) ----------------
// Inputs must be pre-rounded to tf32 bit patterns. No CVT in the inner loop.
// ACT: 0 none, 1 sigmoid, 2 tanh.  ROUND: round outputs to tf32 on store.
template <int ACT, int ROUND>
__global__ __launch_bounds__(256, 2)
void gemm_tf32(const float* __restrict__ A, const float* __restrict__ B,
               float* __restrict__ C, int M, int N, int K, int ldc,
               const float* __restrict__ bias)
{
    extern __shared__ float sm[];
    float* AsBase = sm;                 // [2][BM][ASTRIDE]
    float* BsBase = sm + 2 * A_STAGE;   // [2][BK][BSTRIDE]

    const int tid  = threadIdx.x;
    const int wid  = tid >> 5;
    const int lane = tid & 31;
    const int wm   = (wid >> 2) * 64;   // 0 / 64
    const int wn   = (wid & 3) * 32;    // 0..96
    const int lr   = lane >> 2;         // 0..7
    const int lc   = lane & 3;          // 0..3

    const int brow = blockIdx.y * BM;
    const int bcol = blockIdx.x * BN;

    const float* Ag = A + (size_t)brow * K;
    const float* Bg = B + bcol;

    float acc[4][4][4];
#pragma unroll
    for (int mi = 0; mi < 4; mi++)
#pragma unroll
        for (int ni = 0; ni < 4; ni++)
#pragma unroll
            for (int e = 0; e < 4; e++) acc[mi][ni][e] = 0.f;

    const int ntiles = K / BK;

#define LOAD_TILE(kt, stg)                                                      \
    {                                                                           \
        const int k0 = (kt) * BK;                                               \
        float* As_ = AsBase + (stg) * A_STAGE;                                  \
        float* Bs_ = BsBase + (stg) * B_STAGE;                                  \
        _Pragma("unroll")                                                       \
        for (int i = 0; i < 4; i++) {                                           \
            int c   = tid + i * 256;                                            \
            int row = c >> 3;                                                   \
            int kc  = (c & 7) * 4;                                              \
            cpasync16(As_ + row * ASTRIDE + kc, Ag + (size_t)row * K + k0 + kc);\
        }                                                                       \
        _Pragma("unroll")                                                       \
        for (int i = 0; i < 4; i++) {                                           \
            int c   = tid + i * 256;                                            \
            int row = c >> 5;                                                   \
            int nc  = (c & 31) * 4;                                             \
            cpasync16(Bs_ + row * BSTRIDE + nc, Bg + (size_t)(k0 + row) * N + nc);\
        }                                                                       \
        asm volatile("cp.async.commit_group;\n" ::: "memory");                  \
    }

    LOAD_TILE(0, 0);

    for (int kt = 0; kt < ntiles; kt++) {
        const int cur = kt & 1;
        if (kt + 1 < ntiles) {
            LOAD_TILE(kt + 1, (kt + 1) & 1);
            asm volatile("cp.async.wait_group 1;\n" ::: "memory");
        } else {
            asm volatile("cp.async.wait_group 0;\n" ::: "memory");
        }
        __syncthreads();

        const uint32_t* As_ = (const uint32_t*)(AsBase + cur * A_STAGE);
        const uint32_t* Bs_ = (const uint32_t*)(BsBase + cur * B_STAGE);

#pragma unroll
        for (int ks = 0; ks < BK / 8; ks++) {
            const int kk = ks * 8;
            uint32_t a[4][4];
#pragma unroll
            for (int mi = 0; mi < 4; mi++) {
                const uint32_t* ap = As_ + (wm + mi * 16 + lr) * ASTRIDE + kk;
                a[mi][0] = ap[lc];
                a[mi][1] = ap[8 * ASTRIDE + lc];
                a[mi][2] = ap[lc + 4];
                a[mi][3] = ap[8 * ASTRIDE + lc + 4];
            }
            uint32_t b[4][2];
#pragma unroll
            for (int ni = 0; ni < 4; ni++) {
                const uint32_t* bp = Bs_ + (kk + lc) * BSTRIDE + wn + ni * 8 + lr;
                b[ni][0] = bp[0];
                b[ni][1] = bp[4 * BSTRIDE];
            }
#pragma unroll
            for (int mi = 0; mi < 4; mi++)
#pragma unroll
                for (int ni = 0; ni < 4; ni++)
                    mma_tf32(acc[mi][ni], a[mi], b[ni]);
        }
        __syncthreads();
    }
#undef LOAD_TILE

    // ---- epilogue ----
#pragma unroll
    for (int mi = 0; mi < 4; mi++) {
        const int r0 = brow + wm + mi * 16 + lr;
#pragma unroll
        for (int ni = 0; ni < 4; ni++) {
            const int col = bcol + wn + ni * 8 + lc * 2;
            float v[4];
#pragma unroll
            for (int e = 0; e < 4; e++) v[e] = acc[mi][ni][e];
            if (bias) {
                float b0 = bias[col], b1 = bias[col + 1];
                v[0] += b0; v[1] += b1; v[2] += b0; v[3] += b1;
            }
#pragma unroll
            for (int e = 0; e < 4; e++) {
                if (ACT == 1) v[e] = __fdividef(1.f, 1.f + __expf(-v[e]));
                if (ACT == 2) v[e] = __fdividef(2.f, 1.f + __expf(-2.f * v[e])) - 1.f;
                if (ROUND)    v[e] = roundtf(v[e]);
            }
            *(float2*)(C + (size_t)r0 * ldc + col)       = make_float2(v[0], v[1]);
            *(float2*)(C + (size_t)(r0 + 8) * ldc + col) = make_float2(v[2], v[3]);
        }
    }
}

// ---------------- transpose: dst[C,R] = src[R,C]^T (optional tf32 rounding) ----------------
template <int ROUND>
__global__ void transpose_k(const float* __restrict__ src, float* __restrict__ dst,
                            int R, int C)
{
    __shared__ float t[32][33];
    int c = blockIdx.x * 32 + threadIdx.x;
    int r = blockIdx.y * 32 + threadIdx.y;
#pragma unroll
    for (int i = 0; i < 32; i += 8)
        if (r + i < R && c < C) t[threadIdx.y + i][threadIdx.x] = src[(size_t)(r + i) * C + c];
    __syncthreads();
    int c2 = blockIdx.y * 32 + threadIdx.x;
    int r2 = blockIdx.x * 32 + threadIdx.y;
#pragma unroll
    for (int i = 0; i < 32; i += 8)
        if (r2 + i < C && c2 < R) {
            float v = t[threadIdx.x][threadIdx.y + i];
            dst[(size_t)(r2 + i) * R + c2] = ROUND ? roundtf(v) : v;
        }
}

// rounded strided block copy: dst[r*ldd + c] = round(src[r*lds + c]), r<rows, c<cols
__global__ void blockcopy_round_k(const float* __restrict__ src, float* __restrict__ dst,
                                  int rows, int cols, int lds, int ldd)
{
    long i = (long)blockIdx.x * 256 + threadIdx.x;
    long n = (long)rows * cols;
    if (i < n) {
        long r = i / cols, c = i - r * cols;
        dst[r * ldd + c] = roundtf(src[r * lds + c]);
    }
}

// U[:,2h:3h] = round(r * nodes); r strided in gZR
__global__ void rnmul_k(const float* __restrict__ ZR, const float* __restrict__ Nd,
                        float* __restrict__ Uslot)
{
    long i = (long)blockIdx.x * 256 + threadIdx.x;
    if (i < (long)NC * H) {
        long r = i / H, c = i - r * H;
        Uslot[r * H3 + c] = roundtf(ZR[r * H2 + H + c] * Nd[i]);
    }
}

// nodes = (1-z)*nodes + z*h ; refresh rounded copies
__global__ void update_k(const float* __restrict__ ZR, const float* __restrict__ Hv,
                         float* __restrict__ Nd, float* __restrict__ NdR,
                         float* __restrict__ Uslot)
{
    long i = (long)blockIdx.x * 256 + threadIdx.x;
    if (i < (long)NC * H) {
        long r = i / H, c = i - r * H;
        float z = ZR[r * H2 + c];
        float nv = (1.f - z) * Nd[i] + z * Hv[i];
        Nd[i] = nv;
        float nr = roundtf(nv);
        NdR[i] = nr;
        Uslot[r * H3 + c] = nr;
    }
}

// deterministic two-pass sum of squares
__global__ void l2part_k(const float* __restrict__ S, long n, float* __restrict__ part)
{
    __shared__ float sm[256];
    float s = 0.f;
    for (long i = (long)blockIdx.x * 256 + threadIdx.x; i < n; i += 256L * 256L) {
        float v = S[i];
        s = fmaf(v, v, s);
    }
    sm[threadIdx.x] = s;
    __syncthreads();
    for (int o = 128; o > 0; o >>= 1) {
        if (threadIdx.x < o) sm[threadIdx.x] += sm[threadIdx.x + o];
        __syncthreads();
    }
    if (threadIdx.x == 0) part[blockIdx.x] = sm[0];
}

__global__ void l2final_k(const float* __restrict__ part, float* __restrict__ out)
{
    __shared__ float sm[256];
    sm[threadIdx.x] = part[threadIdx.x];
    __syncthreads();
    for (int o = 128; o > 0; o >>= 1) {
        if (threadIdx.x < o) sm[threadIdx.x] += sm[threadIdx.x + o];
        __syncthreads();
    }
    if (threadIdx.x == 0) out[0] = sm[0];
}

// ---------------- launch ----------------
extern "C" void kernel_launch(void* const* d_in, const int* in_sizes, int n_in,
                              void* d_out, int out_size)
{
    const float* x   = (const float*)d_in[0];   // [B, h]
    const float* lfw = (const float*)d_in[1];   // [h, N]
    const float* inm = (const float*)d_in[2];   // [N, N]
    const float* w3w = (const float*)d_in[3];   // [2h, h]
    const float* w3u = (const float*)d_in[4];   // [h, h]
    const float* w4w = (const float*)d_in[5];
    const float* w4u = (const float*)d_in[6];
    const float* w5w = (const float*)d_in[7];
    const float* w5u = (const float*)d_in[8];
    const float* fcw = (const float*)d_in[9];   // [2h, h]
    const float* fcb = (const float*)d_in[10];  // [h]
    float* out = (float*)d_out;

    float *pInR, *pOutT, *pInit, *pNodes, *pNodesR, *pU, *pW34, *pW5, *pFcw;
    float *pZR, *pH, *pV, *pS, *pWt, *pXr, *pPart;
    cudaGetSymbolAddress((void**)&pInR, gInR);
    cudaGetSymbolAddress((void**)&pOutT, gOutT);
    cudaGetSymbolAddress((void**)&pInit, gInit);
    cudaGetSymbolAddress((void**)&pNodes, gNodes);
    cudaGetSymbolAddress((void**)&pNodesR, gNodesR);
    cudaGetSymbolAddress((void**)&pU, gU);
    cudaGetSymbolAddress((void**)&pW34, gW34);
    cudaGetSymbolAddress((void**)&pW5, gW5);
    cudaGetSymbolAddress((void**)&pFcw, gFcw);
    cudaGetSymbolAddress((void**)&pZR, gZR);
    cudaGetSymbolAddress((void**)&pH, gHh);
    cudaGetSymbolAddress((void**)&pV, gV);
    cudaGetSymbolAddress((void**)&pS, gS);
    cudaGetSymbolAddress((void**)&pWt, gWt);
    cudaGetSymbolAddress((void**)&pXr, gXr);
    cudaGetSymbolAddress((void**)&pPart, gPart);

    cudaFuncSetAttribute(gemm_tf32<0,0>, cudaFuncAttributeMaxDynamicSharedMemorySize, SMEM_BYTES);
    cudaFuncSetAttribute(gemm_tf32<0,1>, cudaFuncAttributeMaxDynamicSharedMemorySize, SMEM_BYTES);
    cudaFuncSetAttribute(gemm_tf32<1,0>, cudaFuncAttributeMaxDynamicSharedMemorySize, SMEM_BYTES);
    cudaFuncSetAttribute(gemm_tf32<2,0>, cudaFuncAttributeMaxDynamicSharedMemorySize, SMEM_BYTES);

    const size_t F = sizeof(float);
    auto grid1 = [](long n) { return (int)((n + 255) / 256); };

    // ---- prep: rounded operand buffers ----
    // adjacency
    blockcopy_round_k<<<grid1((long)NC * NC), 256>>>(inm, pInR, NC, NC, NC, NC);
    dim3 tb(32, 8);
    transpose_k<1><<<dim3(NC / 32, NC / 32), tb>>>(inm, pOutT, NC, NC);
    // init nodes: full + rounded
    transpose_k<0><<<dim3(NC / 32, H / 32), tb>>>(lfw, pInit, H, NC);
    transpose_k<1><<<dim3(NC / 32, H / 32), tb>>>(lfw, pNodesR, H, NC);
    cudaMemcpyAsync(pNodes, pInit, (size_t)NC * H * F, cudaMemcpyDeviceToDevice, 0);
    // gate weights: gW34 = [w3w|w4w ; w3u|w4u]  (H3 x H2), gW5 = [w5w ; w5u] (H3 x H)
    blockcopy_round_k<<<grid1((long)H2 * H), 256>>>(w3w, pW34,                       H2, H, H, H2);
    blockcopy_round_k<<<grid1((long)H2 * H), 256>>>(w4w, pW34 + H,                   H2, H, H, H2);
    blockcopy_round_k<<<grid1((long)H  * H), 256>>>(w3u, pW34 + (size_t)H2 * H2,     H,  H, H, H2);
    blockcopy_round_k<<<grid1((long)H  * H), 256>>>(w4u, pW34 + (size_t)H2 * H2 + H, H,  H, H, H2);
    blockcopy_round_k<<<grid1((long)H2 * H), 256>>>(w5w, pW5,                        H2, H, H, H);
    blockcopy_round_k<<<grid1((long)H  * H), 256>>>(w5u, pW5 + (size_t)H2 * H,       H,  H, H, H);
    blockcopy_round_k<<<grid1((long)H2 * H), 256>>>(fcw, pFcw, H2, H, H, H);
    blockcopy_round_k<<<grid1((long)BB * H), 256>>>(x,   pXr,  BB, H, H, H);

    const long nh = (long)NC * H;
    const int ewg = grid1(nh);
    // U slot3 = round(init nodes)
    blockcopy_round_k<<<grid1(nh), 256>>>(pInit, pU + H2, NC, H, H, H3);

    dim3 g_nh(H / 128, NC / 128);       // [N, h] outputs
    dim3 g_zr(H2 / 128, NC / 128);      // [N, 2h] output (fused z|r)

    for (int t = 0; t < 3; t++) {
        gemm_tf32<0,1><<<g_nh, 256, SMEM_BYTES>>>(pInR,  pNodesR, pU,     NC, H,  NC, H3, nullptr);
        gemm_tf32<0,1><<<g_nh, 256, SMEM_BYTES>>>(pOutT, pNodesR, pU + H, NC, H,  NC, H3, nullptr);
        gemm_tf32<1,0><<<g_zr, 256, SMEM_BYTES>>>(pU, pW34, pZR, NC, H2, H3, H2, nullptr);  // [z|r]
        rnmul_k<<<ewg, 256>>>(pZR, pNodes, pU + H2);                                        // slot3 = r*n
        gemm_tf32<2,0><<<g_nh, 256, SMEM_BYTES>>>(pU, pW5, pH, NC, H, H3, H, nullptr);      // hv
        update_k<<<ewg, 256>>>(pZR, pH, pNodes, pNodesR, pU + H2);
    }

    // step_out = [nodes | init] @ fc_out_w + b
    blockcopy_round_k<<<grid1(nh), 256>>>(pNodes, pV,     NC, H, H, H2);
    blockcopy_round_k<<<grid1(nh), 256>>>(pInit,  pV + H, NC, H, H, H2);
    gemm_tf32<0,0><<<g_nh, 256, SMEM_BYTES>>>(pV, pFcw, pS, NC, H, H2, H, fcb);

    // weight = step_out^T ; output = x @ weight
    transpose_k<1><<<dim3(H / 32, NC / 32), tb>>>(pS, pWt, NC, H);
    gemm_tf32<0,0><<<dim3(NC / 128, BB / 128), 256, SMEM_BYTES>>>(pXr, pWt, out, BB, NC, H, NC, nullptr);

    // l2_reg = sum(step_out^2)
    l2part_k<<<256, 256>>>(pS, nh, pPart);
    if ((long)out_size > (long)BB * NC)
        l2final_k<<<1, 256>>>(pPart, out + (size_t)BB * NC);
}

// round 10
// speedup vs baseline: 3.7853x; 1.0031x over previous
#include <cuda_runtime.h>
#include <math.h>
#include <stdint.h>

#define H   1024
#define NC  2048
#define BB  8192
#define H2  2048
#define H3  3072

#define BM 128
#define BN 128
#define BK 32
#define ASTRIDE 40    // BK + 8 : a-frag LDS.64 banks (8lr + 2lc) conflict-free
#define BSTRIDE 132   // BN + 4 : b-frag banks (8lc + lr) conflict-free
#define A_STAGE (BM * ASTRIDE)          // 5120 floats
#define B_STAGE (BK * BSTRIDE)          // 4224 floats
#define SMEM_FLOATS (2 * A_STAGE + 2 * B_STAGE)
#define SMEM_BYTES (SMEM_FLOATS * 4)    // 74752 B

// ---------------- scratch (no allocations allowed) ----------------
// All GEMM-operand buffers hold tf32-RNA pre-rounded fp32 bits.
__device__ float gAdj  [(size_t)2 * NC * NC]; // [round(in_matrix); round(in_matrix^T)]
__device__ float gInit [(size_t)NC * H];    // last_fc_weight^T (full precision)
__device__ float gNodes[(size_t)NC * H];    // full precision state
__device__ float gNodesR[(size_t)NC * H];   // round(nodes) — GEMM B operand
__device__ float gU    [(size_t)NC * H3];   // rounded [in@n | out@n | n or rv*n]
__device__ float gW34  [(size_t)H3 * H2];   // rounded [w3w|w4w ; w3u|w4u]
__device__ float gW5   [(size_t)H3 * H];    // rounded [w5w ; w5u]
__device__ float gFcw  [(size_t)H2 * H];    // rounded fc_out_w
__device__ float gZR   [(size_t)NC * H2];   // sigmoid outputs [z | r] (full)
__device__ float gHh   [(size_t)NC * H];    // tanh output (full)
__device__ float gV    [(size_t)NC * H2];   // rounded [nodes | init]
__device__ float gS    [(size_t)NC * H];    // step_out (full, for l2)
__device__ float gWt   [(size_t)H * NC];    // rounded step_out^T
__device__ float gXr   [(size_t)BB * H];    // rounded x
__device__ float gPart [256];

// ---------------- helpers ----------------
__device__ __forceinline__ uint32_t f2tf32(float x) {
    uint32_t r;
    asm volatile("cvt.rna.tf32.f32 %0, %1;\n" : "=r"(r) : "f"(x));
    return r;
}
__device__ __forceinline__ float roundtf(float x) { return __uint_as_float(f2tf32(x)); }

__device__ __forceinline__ void cpasync16(float* dst_smem, const float* src) {
    uint32_t d = (uint32_t)__cvta_generic_to_shared(dst_smem);
    asm volatile("cp.async.cg.shared.global [%0], [%1], 16;\n" :: "r"(d), "l"(src));
}

__device__ __forceinline__ void mma_tf32(float c[4], const uint32_t a[4], const uint32_t b[2]) {
    asm volatile(
        "mma.sync.aligned.m16n8k8.row.col.f32.tf32.tf32.f32 "
        "{%0,%1,%2,%3}, {%4,%5,%6,%7}, {%8,%9}, {%0,%1,%2,%3};\n"
        : "+f"(c[0]), "+f"(c[1]), "+f"(c[2]), "+f"(c[3])
        : "r"(a[0]), "r"(a[1]), "r"(a[2]), "r"(a[3]), "r"(b[0]), "r"(b[1]));
}

// ---------------- TF32 MMA GEMM: C = act(A @ B (+bias)) ----------------
// Inputs pre-rounded to tf32 bit patterns; no CVT in the inner loop.
// k-relabeled fragments: lane lc's (k_lo,k_hi) slots carry true-k (2lc, 2lc+1)
// -> A-frag pairs are adjacent floats (LDS.64); B rows kk+2lc / kk+2lc+1.
// ACT: 0 none, 1 sigmoid, 2 tanh.  ROUND: round outputs to tf32 on store.
// AGG: A is [inR; outT] stacked (M=2*NC); C row = brow%NC, col offset +H for 2nd half.
template <int ACT, int ROUND, int AGG>
__global__ __launch_bounds__(256, 2)
void gemm_tf32(const float* __restrict__ A, const float* __restrict__ B,
               float* __restrict__ C, int M, int N, int K, int ldc,
               const float* __restrict__ bias)
{
    extern __shared__ float sm[];
    float* AsBase = sm;                 // [2][BM][ASTRIDE]
    float* BsBase = sm + 2 * A_STAGE;   // [2][BK][BSTRIDE]

    const int tid  = threadIdx.x;
    const int wid  = tid >> 5;
    const int lane = tid & 31;
    const int wm   = (wid >> 2) * 64;   // 0 / 64
    const int wn   = (wid & 3) * 32;    // 0..96
    const int lr   = lane >> 2;         // 0..7
    const int lc   = lane & 3;          // 0..3

    const int brow = blockIdx.y * BM;
    const int bcol = blockIdx.x * BN;

    const float* Ag = A + (size_t)brow * K;
    const float* Bg = B + bcol;

    float acc[4][4][4];
#pragma unroll
    for (int mi = 0; mi < 4; mi++)
#pragma unroll
        for (int ni = 0; ni < 4; ni++)
#pragma unroll
            for (int e = 0; e < 4; e++) acc[mi][ni][e] = 0.f;

    const int ntiles = K / BK;

#define LOAD_TILE(kt, stg)                                                      \
    {                                                                           \
        const int k0 = (kt) * BK;                                               \
        float* As_ = AsBase + (stg) * A_STAGE;                                  \
        float* Bs_ = BsBase + (stg) * B_STAGE;                                  \
        _Pragma("unroll")                                                       \
        for (int i = 0; i < 4; i++) {                                           \
            int c   = tid + i * 256;                                            \
            int row = c >> 3;                                                   \
            int kc  = (c & 7) * 4;                                              \
            cpasync16(As_ + row * ASTRIDE + kc, Ag + (size_t)row * K + k0 + kc);\
        }                                                                       \
        _Pragma("unroll")                                                       \
        for (int i = 0; i < 4; i++) {                                           \
            int c   = tid + i * 256;                                            \
            int row = c >> 5;                                                   \
            int nc  = (c & 31) * 4;                                             \
            cpasync16(Bs_ + row * BSTRIDE + nc, Bg + (size_t)(k0 + row) * N + nc);\
        }                                                                       \
        asm volatile("cp.async.commit_group;\n" ::: "memory");                  \
    }

    LOAD_TILE(0, 0);

    for (int kt = 0; kt < ntiles; kt++) {
        const int cur = kt & 1;
        if (kt + 1 < ntiles) {
            LOAD_TILE(kt + 1, (kt + 1) & 1);
            asm volatile("cp.async.wait_group 1;\n" ::: "memory");
        } else {
            asm volatile("cp.async.wait_group 0;\n" ::: "memory");
        }
        __syncthreads();

        const uint32_t* As_ = (const uint32_t*)(AsBase + cur * A_STAGE);
        const uint32_t* Bs_ = (const uint32_t*)(BsBase + cur * B_STAGE);

#pragma unroll
        for (int ks = 0; ks < BK / 8; ks++) {
            const int kk = ks * 8;
            uint32_t a[4][4];
#pragma unroll
            for (int mi = 0; mi < 4; mi++) {
                const uint32_t* ap = As_ + (wm + mi * 16 + lr) * ASTRIDE + kk + 2 * lc;
                uint2 lo = *(const uint2*)ap;
                uint2 hi = *(const uint2*)(ap + 8 * ASTRIDE);
                a[mi][0] = lo.x;   // slot k_lo  <- true k = 2lc
                a[mi][2] = lo.y;   // slot k_hi  <- true k = 2lc+1
                a[mi][1] = hi.x;
                a[mi][3] = hi.y;
            }
            uint32_t b[4][2];
#pragma unroll
            for (int ni = 0; ni < 4; ni++) {
                const uint32_t* bp = Bs_ + (kk + 2 * lc) * BSTRIDE + wn + ni * 8 + lr;
                b[ni][0] = bp[0];          // true k = 2lc
                b[ni][1] = bp[BSTRIDE];    // true k = 2lc+1
            }
#pragma unroll
            for (int mi = 0; mi < 4; mi++)
#pragma unroll
                for (int ni = 0; ni < 4; ni++)
                    mma_tf32(acc[mi][ni], a[mi], b[ni]);
        }
        __syncthreads();
    }
#undef LOAD_TILE

    // ---- epilogue ----
    const int browc = AGG ? (brow & (NC - 1)) : brow;
    const int cofs  = AGG ? ((brow >= NC) ? H : 0) : 0;
#pragma unroll
    for (int mi = 0; mi < 4; mi++) {
        const int r0 = browc + wm + mi * 16 + lr;
#pragma unroll
        for (int ni = 0; ni < 4; ni++) {
            const int col = cofs + bcol + wn + ni * 8 + lc * 2;
            float v[4];
#pragma unroll
            for (int e = 0; e < 4; e++) v[e] = acc[mi][ni][e];
            if (bias) {
                float b0 = bias[col - cofs], b1 = bias[col - cofs + 1];
                v[0] += b0; v[1] += b1; v[2] += b0; v[3] += b1;
            }
#pragma unroll
            for (int e = 0; e < 4; e++) {
                if (ACT == 1) v[e] = __fdividef(1.f, 1.f + __expf(-v[e]));
                if (ACT == 2) v[e] = __fdividef(2.f, 1.f + __expf(-2.f * v[e])) - 1.f;
                if (ROUND)    v[e] = roundtf(v[e]);
            }
            *(float2*)(C + (size_t)r0 * ldc + col)       = make_float2(v[0], v[1]);
            *(float2*)(C + (size_t)(r0 + 8) * ldc + col) = make_float2(v[2], v[3]);
        }
    }
}

// ---------------- transpose: dst[C,R] = src[R,C]^T (optional tf32 rounding) ----------------
template <int ROUND>
__global__ void transpose_k(const float* __restrict__ src, float* __restrict__ dst,
                            int R, int C)
{
    __shared__ float t[32][33];
    int c = blockIdx.x * 32 + threadIdx.x;
    int r = blockIdx.y * 32 + threadIdx.y;
#pragma unroll
    for (int i = 0; i < 32; i += 8)
        if (r + i < R && c < C) t[threadIdx.y + i][threadIdx.x] = src[(size_t)(r + i) * C + c];
    __syncthreads();
    int c2 = blockIdx.y * 32 + threadIdx.x;
    int r2 = blockIdx.x * 32 + threadIdx.y;
#pragma unroll
    for (int i = 0; i < 32; i += 8)
        if (r2 + i < C && c2 < R) {
            float v = t[threadIdx.x][threadIdx.y + i];
            dst[(size_t)(r2 + i) * R + c2] = ROUND ? roundtf(v) : v;
        }
}

// rounded strided block copy: dst[r*ldd + c] = round(src[r*lds + c])
__global__ void blockcopy_round_k(const float* __restrict__ src, float* __restrict__ dst,
                                  int rows, int cols, int lds, int ldd)
{
    long i = (long)blockIdx.x * 256 + threadIdx.x;
    long n = (long)rows * cols;
    if (i < n) {
        long r = i / cols, c = i - r * cols;
        dst[r * ldd + c] = roundtf(src[r * lds + c]);
    }
}

// U[:,2h:3h] = round(r * nodes); r strided in gZR
__global__ void rnmul_k(const float* __restrict__ ZR, const float* __restrict__ Nd,
                        float* __restrict__ Uslot)
{
    long i = (long)blockIdx.x * 256 + threadIdx.x;
    if (i < (long)NC * H) {
        long r = i / H, c = i - r * H;
        Uslot[r * H3 + c] = roundtf(ZR[r * H2 + H + c] * Nd[i]);
    }
}

// nodes = (1-z)*nodes + z*h ; refresh rounded copies
__global__ void update_k(const float* __restrict__ ZR, const float* __restrict__ Hv,
                         float* __restrict__ Nd, float* __restrict__ NdR,
                         float* __restrict__ Uslot)
{
    long i = (long)blockIdx.x * 256 + threadIdx.x;
    if (i < (long)NC * H) {
        long r = i / H, c = i - r * H;
        float z = ZR[r * H2 + c];
        float nv = (1.f - z) * Nd[i] + z * Hv[i];
        Nd[i] = nv;
        float nr = roundtf(nv);
        NdR[i] = nr;
        Uslot[r * H3 + c] = nr;
    }
}

// deterministic two-pass sum of squares
__global__ void l2part_k(const float* __restrict__ S, long n, float* __restrict__ part)
{
    __shared__ float sm[256];
    float s = 0.f;
    for (long i = (long)blockIdx.x * 256 + threadIdx.x; i < n; i += 256L * 256L) {
        float v = S[i];
        s = fmaf(v, v, s);
    }
    sm[threadIdx.x] = s;
    __syncthreads();
    for (int o = 128; o > 0; o >>= 1) {
        if (threadIdx.x < o) sm[threadIdx.x] += sm[threadIdx.x + o];
        __syncthreads();
    }
    if (threadIdx.x == 0) part[blockIdx.x] = sm[0];
}

__global__ void l2final_k(const float* __restrict__ part, float* __restrict__ out)
{
    __shared__ float sm[256];
    sm[threadIdx.x] = part[threadIdx.x];
    __syncthreads();
    for (int o = 128; o > 0; o >>= 1) {
        if (threadIdx.x < o) sm[threadIdx.x] += sm[threadIdx.x + o];
        __syncthreads();
    }
    if (threadIdx.x == 0) out[0] = sm[0];
}

// ---------------- launch ----------------
extern "C" void kernel_launch(void* const* d_in, const int* in_sizes, int n_in,
                              void* d_out, int out_size)
{
    const float* x   = (const float*)d_in[0];   // [B, h]
    const float* lfw = (const float*)d_in[1];   // [h, N]
    const float* inm = (const float*)d_in[2];   // [N, N]
    const float* w3w = (const float*)d_in[3];   // [2h, h]
    const float* w3u = (const float*)d_in[4];   // [h, h]
    const float* w4w = (const float*)d_in[5];
    const float* w4u = (const float*)d_in[6];
    const float* w5w = (const float*)d_in[7];
    const float* w5u = (const float*)d_in[8];
    const float* fcw = (const float*)d_in[9];   // [2h, h]
    const float* fcb = (const float*)d_in[10];  // [h]
    float* out = (float*)d_out;

    float *pAdj, *pInit, *pNodes, *pNodesR, *pU, *pW34, *pW5, *pFcw;
    float *pZR, *pH, *pV, *pS, *pWt, *pXr, *pPart;
    cudaGetSymbolAddress((void**)&pAdj, gAdj);
    cudaGetSymbolAddress((void**)&pInit, gInit);
    cudaGetSymbolAddress((void**)&pNodes, gNodes);
    cudaGetSymbolAddress((void**)&pNodesR, gNodesR);
    cudaGetSymbolAddress((void**)&pU, gU);
    cudaGetSymbolAddress((void**)&pW34, gW34);
    cudaGetSymbolAddress((void**)&pW5, gW5);
    cudaGetSymbolAddress((void**)&pFcw, gFcw);
    cudaGetSymbolAddress((void**)&pZR, gZR);
    cudaGetSymbolAddress((void**)&pH, gHh);
    cudaGetSymbolAddress((void**)&pV, gV);
    cudaGetSymbolAddress((void**)&pS, gS);
    cudaGetSymbolAddress((void**)&pWt, gWt);
    cudaGetSymbolAddress((void**)&pXr, gXr);
    cudaGetSymbolAddress((void**)&pPart, gPart);

    cudaFuncSetAttribute(gemm_tf32<0,0,0>, cudaFuncAttributeMaxDynamicSharedMemorySize, SMEM_BYTES);
    cudaFuncSetAttribute(gemm_tf32<0,1,0>, cudaFuncAttributeMaxDynamicSharedMemorySize, SMEM_BYTES);
    cudaFuncSetAttribute(gemm_tf32<0,1,1>, cudaFuncAttributeMaxDynamicSharedMemorySize, SMEM_BYTES);
    cudaFuncSetAttribute(gemm_tf32<1,0,0>, cudaFuncAttributeMaxDynamicSharedMemorySize, SMEM_BYTES);
    cudaFuncSetAttribute(gemm_tf32<2,0,0>, cudaFuncAttributeMaxDynamicSharedMemorySize, SMEM_BYTES);

    const size_t F = sizeof(float);
    auto grid1 = [](long n) { return (int)((n + 255) / 256); };

    // ---- prep: rounded operand buffers ----
    // stacked adjacency [inR; outT]
    blockcopy_round_k<<<grid1((long)NC * NC), 256>>>(inm, pAdj, NC, NC, NC, NC);
    dim3 tb(32, 8);
    transpose_k<1><<<dim3(NC / 32, NC / 32), tb>>>(inm, pAdj + (size_t)NC * NC, NC, NC);
    // init nodes: full + rounded
    transpose_k<0><<<dim3(NC / 32, H / 32), tb>>>(lfw, pInit, H, NC);
    transpose_k<1><<<dim3(NC / 32, H / 32), tb>>>(lfw, pNodesR, H, NC);
    cudaMemcpyAsync(pNodes, pInit, (size_t)NC * H * F, cudaMemcpyDeviceToDevice, 0);
    // gate weights: gW34 = [w3w|w4w ; w3u|w4u]  (H3 x H2), gW5 = [w5w ; w5u] (H3 x H)
    blockcopy_round_k<<<grid1((long)H2 * H), 256>>>(w3w, pW34,                       H2, H, H, H2);
    blockcopy_round_k<<<grid1((long)H2 * H), 256>>>(w4w, pW34 + H,                   H2, H, H, H2);
    blockcopy_round_k<<<grid1((long)H  * H), 256>>>(w3u, pW34 + (size_t)H2 * H2,     H,  H, H, H2);
    blockcopy_round_k<<<grid1((long)H  * H), 256>>>(w4u, pW34 + (size_t)H2 * H2 + H, H,  H, H, H2);
    blockcopy_round_k<<<grid1((long)H2 * H), 256>>>(w5w, pW5,                        H2, H, H, H);
    blockcopy_round_k<<<grid1((long)H  * H), 256>>>(w5u, pW5 + (size_t)H2 * H,       H,  H, H, H);
    blockcopy_round_k<<<grid1((long)H2 * H), 256>>>(fcw, pFcw, H2, H, H, H);
    blockcopy_round_k<<<grid1((long)BB * H), 256>>>(x,   pXr,  BB, H, H, H);

    const long nh = (long)NC * H;
    const int ewg = grid1(nh);
    // U slot3 = round(init nodes)
    blockcopy_round_k<<<grid1(nh), 256>>>(pInit, pU + H2, NC, H, H, H3);

    dim3 g_agg(H / 128, 2 * NC / 128);  // (8, 32) merged in/out aggregation
    dim3 g_nh (H / 128, NC / 128);      // [N, h] outputs
    dim3 g_zr (H2 / 128, NC / 128);     // [N, 2h] output (fused z|r)

    for (int t = 0; t < 3; t++) {
        gemm_tf32<0,1,1><<<g_agg, 256, SMEM_BYTES>>>(pAdj, pNodesR, pU, 2 * NC, H, NC, H3, nullptr);
        gemm_tf32<1,0,0><<<g_zr, 256, SMEM_BYTES>>>(pU, pW34, pZR, NC, H2, H3, H2, nullptr);  // [z|r]
        rnmul_k<<<ewg, 256>>>(pZR, pNodes, pU + H2);                                          // slot3 = r*n
        gemm_tf32<2,0,0><<<g_nh, 256, SMEM_BYTES>>>(pU, pW5, pH, NC, H, H3, H, nullptr);      // hv
        update_k<<<ewg, 256>>>(pZR, pH, pNodes, pNodesR, pU + H2);
    }

    // step_out = [nodes | init] @ fc_out_w + b
    blockcopy_round_k<<<grid1(nh), 256>>>(pNodes, pV,     NC, H, H, H2);
    blockcopy_round_k<<<grid1(nh), 256>>>(pInit,  pV + H, NC, H, H, H2);
    gemm_tf32<0,0,0><<<g_nh, 256, SMEM_BYTES>>>(pV, pFcw, pS, NC, H, H2, H, fcb);

    // weight = step_out^T ; output = x @ weight
    transpose_k<1><<<dim3(H / 32, NC / 32), tb>>>(pS, pWt, NC, H);
    gemm_tf32<0,0,0><<<dim3(NC / 128, BB / 128), 256, SMEM_BYTES>>>(pXr, pWt, out, BB, NC, H, NC, nullptr);

    // l2_reg = sum(step_out^2)
    l2part_k<<<256, 256>>>(pS, nh, pPart);
    if ((long)out_size > (long)BB * NC)
        l2final_k<<<1, 256>>>(pPart, out + (size_t)BB * NC);
}